// round 6
// baseline (speedup 1.0000x reference)
#include <cuda_runtime.h>
#include <stdint.h>
#include <math.h>

// ---------------------------------------------------------------------------
// Static device scratch (no runtime allocation anywhere).
// ---------------------------------------------------------------------------
#define BIG_ELEMS 44302336   // 4*64*416*416
__device__ float g_buf0[BIG_ELEMS];
__device__ float g_buf1[BIG_ELEMS];
__device__ float g_wdup[1340000];    // duplicated weight pairs, all convs
__device__ float g_t[346112];        // 4*128*26*26
__device__ float g_w16a[16];
__device__ float g_w16b[16];
__device__ float g_bnsc[192];        // bn2 @0, bn4 @128
__device__ float g_bnsh[192];

// wdup offsets (floats): layout [ci][co][k=0..8] of (w,w) pairs (18 floats/co)
#define OFF_C1 0
#define OFF_C2 3456
#define OFF_C3 77184
#define OFF_C4 224640
#define OFF_D1 519552
#define OFF_D2 814464
#define OFF_D3 1109376
#define OFF_D4 1256832
#define OFF_D5 1330560

// ---------------------------------------------------------------------------
// f32x2 packed-math helpers
// ---------------------------------------------------------------------------
typedef unsigned long long ull;

__device__ __forceinline__ ull pack2(float lo, float hi) {
    ull r; asm("mov.b64 %0, {%1, %2};" : "=l"(r) : "f"(lo), "f"(hi)); return r;
}
__device__ __forceinline__ void unpack2(ull v, float& lo, float& hi) {
    asm("mov.b64 {%0, %1}, %2;" : "=f"(lo), "=f"(hi) : "l"(v));
}
__device__ __forceinline__ void fma2(ull& a, ull b, ull c) {
    asm("fma.rn.f32x2 %0, %1, %2, %0;" : "+l"(a) : "l"(b), "l"(c));
}

// ---------------------------------------------------------------------------
// cp.async helpers
// ---------------------------------------------------------------------------
__device__ __forceinline__ void cpa4(unsigned int dst, const float* src, bool ok) {
    asm volatile("cp.async.ca.shared.global [%0], [%1], 4, %2;\n"
                 :: "r"(dst), "l"(src), "r"(ok ? 4u : 0u));
}
__device__ __forceinline__ void cpa16(unsigned int dst, const float* src) {
    asm volatile("cp.async.cg.shared.global [%0], [%1], 16;\n"
                 :: "r"(dst), "l"(src));
}
__device__ __forceinline__ void cpa_commit() {
    asm volatile("cp.async.commit_group;\n");
}
template<int N>
__device__ __forceinline__ void cpa_wait() {
    asm volatile("cp.async.wait_group %0;\n" :: "n"(N));
}

// ---------------------------------------------------------------------------
// Weight prep: wd[((ci*Co+co)*9+k)*2 + {0,1}] = w[(co*Cin+ci)*9+k]
// ---------------------------------------------------------------------------
__global__ void wdup_k(const float* __restrict__ w, float* __restrict__ wd,
                       int Cin, int Co)
{
    int total = Cin * Co * 9;
    for (int i = blockIdx.x * blockDim.x + threadIdx.x; i < total;
         i += gridDim.x * blockDim.x) {
        int k  = i % 9;
        int co = (i / 9) % Co;
        int ci = i / (9 * Co);
        float v = w[((size_t)co * Cin + ci) * 9 + k];
        wd[2 * i]     = v;
        wd[2 * i + 1] = v;
    }
}

// ---------------------------------------------------------------------------
// Direct 3x3 conv, pad=1, stride=1, NCHW, fp32 (packed f32x2 math).
// 256 threads -> 32x32 output tile, 2x2 outputs/thread (x-pair packed f32x2),
// COPB output channels per block. 3-stage cp.async pipeline, 1 barrier/ci.
// Weights: pre-duplicated pairs, LDS.64 broadcast (no pack in hot loop).
// ACT: 0=none 1=relu 2=sigmoid; BN scale/shift after relu; POOL fuses 2x2 max.
// ---------------------------------------------------------------------------
template<int COPB, int ACT, bool BN, bool POOL>
__global__ void __launch_bounds__(256, 2)
conv3x3_k(const float* __restrict__ in, const float* __restrict__ wd,
          const float* __restrict__ bias, float* __restrict__ out,
          int N, int Cin, int Co, int H, int W,
          const float* __restrict__ bnsc, const float* __restrict__ bnsh)
{
    __shared__ __align__(16) float s_in[3][1160];       // 34x34 halo tile
    __shared__ __align__(16) float s_w[3][COPB * 18];   // 9 (w,w) pairs per co

    const int tid = threadIdx.x;
    const int tx = tid & 15;
    const int ty = tid >> 4;
    const int tile_x = blockIdx.x * 32;
    const int tile_y = blockIdx.y * 32;
    const int co_blocks = Co / COPB;
    const int n   = blockIdx.z / co_blocks;
    const int co0 = (blockIdx.z % co_blocks) * COPB;

    const float* inN = in + (size_t)n * Cin * H * W;

    // ---- hoist ci-invariant halo-load addressing ----
    int  h_off[5];
    bool h_ok[5];
#pragma unroll
    for (int k = 0; k < 5; k++) {
        int idx = tid + k * 256;
        h_ok[k] = false; h_off[k] = 0;
        if (idx < 1156) {
            int iy = tile_y - 1 + idx / 34;
            int ix = tile_x - 1 + idx % 34;
            bool ok = (iy >= 0 && iy < H && ix >= 0 && ix < W);
            h_ok[k]  = ok;
            h_off[k] = ok ? iy * W + ix : 0;
        }
    }

    unsigned int s_in_a[3], s_w_a[3];
#pragma unroll
    for (int s = 0; s < 3; s++) {
        s_in_a[s] = (unsigned int)__cvta_generic_to_shared(&s_in[s][0]);
        s_w_a[s]  = (unsigned int)__cvta_generic_to_shared(&s_w[s][0]);
    }

    const int wchunks = COPB * 18 / 4;   // 16B chunks of weight pairs

    auto issue_stage = [&](int ci, int s) {
        const float* inC = inN + (size_t)ci * H * W;
#pragma unroll
        for (int k = 0; k < 5; k++) {
            int idx = tid + k * 256;
            if (idx < 1156)
                cpa4(s_in_a[s] + (unsigned int)idx * 4u, inC + h_off[k], h_ok[k]);
        }
        if (tid < wchunks)
            cpa16(s_w_a[s] + (unsigned int)tid * 16u,
                  wd + ((size_t)ci * Co + co0) * 18 + tid * 4);
        cpa_commit();
    };

    ull acc[COPB][2];
#pragma unroll
    for (int j = 0; j < COPB; j++) { acc[j][0] = 0ull; acc[j][1] = 0ull; }

    issue_stage(0, 0);
    if (Cin > 1) issue_stage(1, 1);

    for (int ci = 0; ci < Cin; ci++) {
        const int s = ci % 3;
        if (ci + 1 < Cin) cpa_wait<1>(); else cpa_wait<0>();
        __syncthreads();
        if (ci + 2 < Cin) issue_stage(ci + 2, (ci + 2) % 3);

        const float* si = s_in[s];
        // 4 rows x 3 overlapping x-pairs
        ull P[4][3];
#pragma unroll
        for (int dy = 0; dy < 4; dy++) {
            const int base = (2 * ty + dy) * 34 + 2 * tx;
            float2 a = *(const float2*)&si[base];
            float2 b = *(const float2*)&si[base + 2];
            P[dy][0] = pack2(a.x, a.y);
            P[dy][1] = pack2(a.y, b.x);
            P[dy][2] = pack2(b.x, b.y);
        }

#pragma unroll
        for (int j = 0; j < COPB; j++) {
            const ull* w9 = (const ull*)&s_w[s][j * 18];
#pragma unroll
            for (int ky = 0; ky < 3; ky++) {
#pragma unroll
                for (int kx = 0; kx < 3; kx++) {
                    ull wp = w9[ky * 3 + kx];          // LDS.64 broadcast
                    fma2(acc[j][0], P[ky    ][kx], wp);
                    fma2(acc[j][1], P[ky + 1][kx], wp);
                }
            }
        }
    }

    // ---- epilogue ----
    const int ox = tile_x + 2 * tx;
    const int oy = tile_y + 2 * ty;
#pragma unroll
    for (int j = 0; j < COPB; j++) {
        int co = co0 + j;
        float bv = __ldg(&bias[co]);
        float sc = 1.f, sh = 0.f;
        if (BN) { sc = __ldg(&bnsc[co]); sh = __ldg(&bnsh[co]); }
        float v0, v1, v2, v3;
        unpack2(acc[j][0], v0, v1);
        unpack2(acc[j][1], v2, v3);
        v0 += bv; v1 += bv; v2 += bv; v3 += bv;
        if (ACT == 1) {
            v0 = fmaxf(v0, 0.f); v1 = fmaxf(v1, 0.f);
            v2 = fmaxf(v2, 0.f); v3 = fmaxf(v3, 0.f);
        }
        if (BN) {
            v0 = v0 * sc + sh; v1 = v1 * sc + sh;
            v2 = v2 * sc + sh; v3 = v3 * sc + sh;
        }
        if (ACT == 2) {
            v0 = 1.f / (1.f + expf(-v0)); v1 = 1.f / (1.f + expf(-v1));
            v2 = 1.f / (1.f + expf(-v2)); v3 = 1.f / (1.f + expf(-v3));
        }
        if (POOL) {
            // thread owns an aligned 2x2 quad -> one pooled output
            if (ox < W && oy < H) {
                float pv = fmaxf(fmaxf(v0, v1), fmaxf(v2, v3));
                out[((size_t)(n * Co + co) * (H >> 1) + (oy >> 1)) * (W >> 1) + (ox >> 1)] = pv;
            }
        } else {
            float* outC = out + (((size_t)n * Co + co) * H) * W;
            if (ox < W) {
                if (oy < H)     *(float2*)&outC[(size_t)oy * W + ox]       = make_float2(v0, v1);
                if (oy + 1 < H) *(float2*)&outC[(size_t)(oy + 1) * W + ox] = make_float2(v2, v3);
            }
        }
    }
}

// ---------------------------------------------------------------------------
// Bilinear 2x upsample, align_corners=True
// ---------------------------------------------------------------------------
__global__ void up2_k(const float* __restrict__ in, float* __restrict__ out,
                      int NC, int H, int W)
{
    int Ho = 2 * H, Wo = 2 * W;
    float sy = (float)(H - 1) / (float)(Ho - 1);
    float sx = (float)(W - 1) / (float)(Wo - 1);
    long total = (long)NC * Ho * Wo;
    for (long i = blockIdx.x * (long)blockDim.x + threadIdx.x; i < total;
         i += (long)gridDim.x * blockDim.x) {
        int xo = (int)(i % Wo);
        int yo = (int)((i / Wo) % Ho);
        long nc = i / ((long)Wo * Ho);
        float ys = yo * sy, xs = xo * sx;
        int y0 = (int)floorf(ys), x0 = (int)floorf(xs);
        int y1 = min(y0 + 1, H - 1), x1 = min(x0 + 1, W - 1);
        float wy = ys - (float)y0, wx = xs - (float)x0;
        const float* p = in + (size_t)nc * H * W;
        float a = p[y0 * W + x0] * (1.f - wy) + p[y1 * W + x0] * wy;
        float b = p[y0 * W + x1] * (1.f - wy) + p[y1 * W + x1] * wy;
        out[i] = a * (1.f - wx) + b * wx;
    }
}

// ---------------------------------------------------------------------------
// Block attention (two rounds fused algebraically):
//   wa[mn] = <x_mn, fold(x)>/676
//   wb[mn] = wa[mn] * <x_mn, fold_w(x, wa)>/676
//   y = x * wa[blk] * wb[blk]
// ---------------------------------------------------------------------------
__global__ void attn_t_k(const float* __restrict__ x, float* __restrict__ t,
                         const float* __restrict__ wgt)
{
    float wl[16];
#pragma unroll
    for (int i = 0; i < 16; i++) wl[i] = wgt ? __ldg(&wgt[i]) : 1.f;

    const int total = 4 * 128 * 26 * 26;
    for (int i = blockIdx.x * blockDim.x + threadIdx.x; i < total;
         i += gridDim.x * blockDim.x) {
        int w  = i % 26;
        int h  = (i / 26) % 26;
        int bc = i / 676;
        const float* p = x + (size_t)bc * 104 * 104;
        float s = 0.f;
#pragma unroll
        for (int k = 0; k < 4; k++)
#pragma unroll
            for (int l = 0; l < 4; l++)
                s += wl[k * 4 + l] * p[(k * 26 + h) * 104 + l * 26 + w];
        t[i] = s;
    }
}

__global__ void attn_w_k(const float* __restrict__ x, const float* __restrict__ t,
                         const float* __restrict__ premul, float* __restrict__ wout)
{
    const int mn = blockIdx.x;
    const int m = mn >> 2, nn = mn & 3;
    const int total = 4 * 128 * 26 * 26;
    float s = 0.f;
    for (int i = threadIdx.x; i < total; i += blockDim.x) {
        int w  = i % 26;
        int h  = (i / 26) % 26;
        int bc = i / 676;
        s += x[(size_t)bc * 104 * 104 + (m * 26 + h) * 104 + nn * 26 + w] * t[i];
    }
    __shared__ float red[1024];
    red[threadIdx.x] = s;
    __syncthreads();
    for (int st = blockDim.x >> 1; st > 0; st >>= 1) {
        if (threadIdx.x < st) red[threadIdx.x] += red[threadIdx.x + st];
        __syncthreads();
    }
    if (threadIdx.x == 0) {
        float v = red[0] * (1.f / 676.f);
        if (premul) v *= premul[mn];
        wout[mn] = v;
    }
}

__global__ void attn_scale2_k(float* __restrict__ x, const float* __restrict__ wa,
                              const float* __restrict__ wb)
{
    const long total = 4L * 128 * 104 * 104;
    for (long i = blockIdx.x * (long)blockDim.x + threadIdx.x; i < total;
         i += (long)gridDim.x * blockDim.x) {
        int j  = (int)(i % 104);
        int ii = (int)((i / 104) % 104);
        int b  = (ii / 26) * 4 + (j / 26);
        x[i] *= wa[b] * wb[b];
    }
}

// ---------------------------------------------------------------------------
// Fold BN into per-channel scale/shift.
// ---------------------------------------------------------------------------
__global__ void bn_prep_k(const float* __restrict__ g, const float* __restrict__ b,
                          const float* __restrict__ m, const float* __restrict__ v,
                          float* __restrict__ sc, float* __restrict__ sh, int C)
{
    int c = blockIdx.x * blockDim.x + threadIdx.x;
    if (c < C) {
        float s = g[c] / sqrtf(v[c] + 1e-5f);
        sc[c] = s;
        sh[c] = b[c] - m[c] * s;
    }
}

// ---------------------------------------------------------------------------
// Host orchestration (graph-capturable: kernel launches only, default stream)
// ---------------------------------------------------------------------------
static inline dim3 conv_grid(int W, int H, int N, int Co, int copb)
{
    return dim3((W + 31) / 32, (H + 31) / 32, N * (Co / copb));
}

extern "C" void kernel_launch(void* const* d_in, const int* in_sizes, int n_in,
                              void* d_out, int out_size)
{
    (void)in_sizes; (void)n_in; (void)out_size;
    const float* x    = (const float*)d_in[0];
    const float* w1   = (const float*)d_in[1];
    const float* b1   = (const float*)d_in[2];
    const float* w2   = (const float*)d_in[3];
    const float* b2   = (const float*)d_in[4];
    const float* w3   = (const float*)d_in[5];
    const float* b3   = (const float*)d_in[6];
    const float* w4   = (const float*)d_in[7];
    const float* b4   = (const float*)d_in[8];
    const float* dw1  = (const float*)d_in[9];
    const float* db1  = (const float*)d_in[10];
    const float* dw2  = (const float*)d_in[11];
    const float* db2  = (const float*)d_in[12];
    const float* dw3  = (const float*)d_in[13];
    const float* db3  = (const float*)d_in[14];
    const float* dw4  = (const float*)d_in[15];
    const float* db4  = (const float*)d_in[16];
    const float* dw5  = (const float*)d_in[17];
    const float* db5  = (const float*)d_in[18];
    const float* bn2g = (const float*)d_in[19];
    const float* bn2b = (const float*)d_in[20];
    const float* bn2m = (const float*)d_in[21];
    const float* bn2v = (const float*)d_in[22];
    const float* bn4g = (const float*)d_in[23];
    const float* bn4b = (const float*)d_in[24];
    const float* bn4m = (const float*)d_in[25];
    const float* bn4v = (const float*)d_in[26];
    float* out = (float*)d_out;

    float *buf0, *buf1, *wd, *tb, *w16a, *w16b, *bnsc, *bnsh;
    cudaGetSymbolAddress((void**)&buf0, g_buf0);
    cudaGetSymbolAddress((void**)&buf1, g_buf1);
    cudaGetSymbolAddress((void**)&wd,   g_wdup);
    cudaGetSymbolAddress((void**)&tb,   g_t);
    cudaGetSymbolAddress((void**)&w16a, g_w16a);
    cudaGetSymbolAddress((void**)&w16b, g_w16b);
    cudaGetSymbolAddress((void**)&bnsc, g_bnsc);
    cudaGetSymbolAddress((void**)&bnsh, g_bnsh);

    // ---- prep: duplicated weight pairs + folded BN ----
    wdup_k<<<16,  256>>>(w1,  wd + OFF_C1, 3,   64);
    wdup_k<<<144, 256>>>(w2,  wd + OFF_C2, 64,  64);
    wdup_k<<<288, 256>>>(w3,  wd + OFF_C3, 64,  128);
    wdup_k<<<576, 256>>>(w4,  wd + OFF_C4, 128, 128);
    wdup_k<<<576, 256>>>(dw1, wd + OFF_D1, 128, 128);
    wdup_k<<<576, 256>>>(dw2, wd + OFF_D2, 128, 128);
    wdup_k<<<288, 256>>>(dw3, wd + OFF_D3, 128, 64);
    wdup_k<<<144, 256>>>(dw4, wd + OFF_D4, 64,  64);
    wdup_k<<<8,   256>>>(dw5, wd + OFF_D5, 64,  2);
    bn_prep_k<<<1, 128>>>(bn2g, bn2b, bn2m, bn2v, bnsc,       bnsh,       128);
    bn_prep_k<<<1, 64 >>>(bn4g, bn4b, bn4m, bn4v, bnsc + 128, bnsh + 128, 64);

    // ---- encoder (pool fused into conv2/conv4 epilogues) ----
    conv3x3_k<8,1,false,false><<<conv_grid(416,416,4,64, 8), 256>>>(x,    wd+OFF_C1, b1, buf0, 4, 3,   64,  416, 416, nullptr, nullptr);
    conv3x3_k<8,1,false,true ><<<conv_grid(416,416,4,64, 8), 256>>>(buf0, wd+OFF_C2, b2, buf1, 4, 64,  64,  416, 416, nullptr, nullptr);
    conv3x3_k<8,1,false,false><<<conv_grid(208,208,4,128,8), 256>>>(buf1, wd+OFF_C3, b3, buf0, 4, 64,  128, 208, 208, nullptr, nullptr);
    conv3x3_k<8,1,false,true ><<<conv_grid(208,208,4,128,8), 256>>>(buf0, wd+OFF_C4, b4, buf1, 4, 128, 128, 208, 208, nullptr, nullptr);

    // ---- fused double block-attention on buf1 [4,128,104,104] ----
    attn_t_k<<<1352, 256>>>(buf1, tb, nullptr);
    attn_w_k<<<16, 1024>>>(buf1, tb, nullptr, w16a);
    attn_t_k<<<1352, 256>>>(buf1, tb, w16a);
    attn_w_k<<<16, 1024>>>(buf1, tb, w16a, w16b);
    attn_scale2_k<<<2048, 256>>>(buf1, w16a, w16b);

    // ---- decoder ----
    conv3x3_k<8,1,false,false><<<conv_grid(104,104,4,128,8), 256>>>(buf1, wd+OFF_D1, db1, buf0, 4, 128, 128, 104, 104, nullptr, nullptr);
    conv3x3_k<8,1,true ,false><<<conv_grid(104,104,4,128,8), 256>>>(buf0, wd+OFF_D2, db2, buf1, 4, 128, 128, 104, 104, bnsc, bnsh);
    up2_k<<<2048, 256>>>(buf1, buf0, 4 * 128, 104, 104);
    conv3x3_k<8,1,false,false><<<conv_grid(208,208,4,64, 8), 256>>>(buf0, wd+OFF_D3, db3, buf1, 4, 128, 64,  208, 208, nullptr, nullptr);
    conv3x3_k<8,1,true ,false><<<conv_grid(208,208,4,64, 8), 256>>>(buf1, wd+OFF_D4, db4, buf0, 4, 64,  64,  208, 208, bnsc + 128, bnsh + 128);
    up2_k<<<4096, 256>>>(buf0, buf1, 4 * 64, 208, 208);
    conv3x3_k<2,2,false,false><<<conv_grid(416,416,4,2,  2), 256>>>(buf1, wd+OFF_D5, db5, out, 4, 64,  2,   416, 416, nullptr, nullptr);
}